// round 9
// baseline (speedup 1.0000x reference)
#include <cuda_runtime.h>

// 4M-step sequential sigmoid recurrence via saturation-collapse chunking.
// Warp-autonomous + software-pipelined: each warp owns 2 spans of 32 chunks
// (one chunk per lane). Staging is split into 4 cp.async commit groups
// (pieces {2,3},{4,5},{6,7},{0,1}) and interleaved with warmup compute;
// pred output for pieces 0-3 is stored while pieces 4-7 compute.
// Sigmoid via single-MUFU tanh.approx: sig(10t) = 0.5*tanh(5t)+0.5.
// Ladder: per-chunk fail flag -> fixup (HW2 warmup) -> serial fallback.

#define LCH   64                 // steps per chunk
#define HW2   512                // fixup warmup
#define CHW   32                 // chunks per warp-span (one per lane)
#define SPW   2                  // spans per warp (persistent)
#define WPB   2                  // warps per block
#define TPB   (WPB*32)
#define ROWB  784                // padded row bytes (768 data + 16), stride/16 odd
#define NROW  (CHW+1)            // 33 rows (row 0 = previous chunk)
#define SPANB (NROW*ROWB)        // 25872 B per warp
#define C5    (5.0f)             // gain/2

__device__ unsigned char g_chunk_fail[65536];
__device__ int g_fail2;

__device__ __forceinline__ float tanha(float t){ float r; asm("tanh.approx.f32 %0, %1;" : "=f"(r) : "f"(t)); return r; }
// n' = sigmoid(10*(n+u-0.5)) = 0.5*tanh(5n + v) + 0.5,  v = 5*(u-0.5)
__device__ __forceinline__ float sg(float n, float v){
    return fmaf(0.5f, tanha(fmaf(C5, n, v)), 0.5f);
}

#define MAKEV(x0,x1,x2) \
    float v0 = fmaf(cw00,(x0), fmaf(cw01,(x1), fmaf(cw02,(x2), cb0))); \
    float v1 = fmaf(cw10,(x0), fmaf(cw11,(x1), fmaf(cw12,(x2), cb1))); \
    float v2 = fmaf(cw20,(x0), fmaf(cw21,(x1), fmaf(cw22,(x2), cb2)));

#define LOADW \
    const float cb0 = C5*(__ldg(b+0)-0.5f), cb1 = C5*(__ldg(b+1)-0.5f), cb2 = C5*(__ldg(b+2)-0.5f); \
    const float cw00=C5*__ldg(W+0), cw01=C5*__ldg(W+1), cw02=C5*__ldg(W+2); \
    const float cw10=C5*__ldg(W+3), cw11=C5*__ldg(W+4), cw12=C5*__ldg(W+5); \
    const float cw20=C5*__ldg(W+6), cw21=C5*__ldg(W+7), cw22=C5*__ldg(W+8);

#define TWOSTEP(x0,x1,x2) do { \
    MAKEV(x0,x1,x2) \
    lo0=sg(lo0,v0); lo1=sg(lo1,v1); lo2=sg(lo2,v2); \
    hi0=sg(hi0,v0); hi1=sg(hi1,v1); hi2=sg(hi2,v2); } while(0)

#define ONESTEPW(x0,x1,x2) do { \
    MAKEV(x0,x1,x2) \
    lo0=sg(lo0,v0); lo1=sg(lo1,v1); lo2=sg(lo2,v2); } while(0)

#define MAINSTEP(x0,x1,x2,pd) do { \
    MAKEV(x0,x1,x2) \
    n0=sg(n0,v0); n1=sg(n1,v1); n2=sg(n2,v2); \
    pd = fmaf((x0),n0, fmaf((x1),n1, (x2)*n2)); } while(0)

#define BLOCK8(OP) do { \
    OP(c0.x,c0.y,c0.z,0); OP(c0.w,c1.x,c1.y,1); \
    OP(c1.z,c1.w,c2.x,2); OP(c2.y,c2.z,c2.w,3); \
    OP(c3.x,c3.y,c3.z,4); OP(c3.w,c4.x,c4.y,5); \
    OP(c4.z,c4.w,c5.x,6); OP(c5.y,c5.z,c5.w,7); } while(0)

#define OP_TWO(x0,x1,x2,j)  TWOSTEP(x0,x1,x2)
#define OP_ONE(x0,x1,x2,j)  ONESTEPW(x0,x1,x2)
#define OP_MAIN(x0,x1,x2,j) MAINSTEP(x0,x1,x2,p##j)

#define WAITG(n) asm volatile("cp.async.wait_group %0;" :: "n"(n) : "memory")

// Warmup one 8-step piece of the previous chunk (row = lane).
#define WARMP(p) do { \
    const float4* pc = (const float4*)(wrow + (p)*96); \
    float4 c0=pc[0],c1=pc[1],c2=pc[2],c3=pc[3],c4=pc[4],c5=pc[5]; \
    if (!ucol) { \
        BLOCK8(OP_TWO); \
        col = (lo0==hi0)&&(lo1==hi1)&&(lo2==hi2); \
        ucol = __all_sync(0xffffffffu, col); \
    } else { BLOCK8(OP_ONE); } } while(0)

__global__ void __launch_bounds__(TPB)
scan_warp(const float* __restrict__ x, const float* __restrict__ W,
          const float* __restrict__ b, const float* __restrict__ net0,
          float* __restrict__ out)
{
    extern __shared__ char smem_raw[];
    const int w    = threadIdx.x >> 5;
    const int lane = threadIdx.x & 31;
    const long warpid = (long)blockIdx.x * WPB + w;
    char* sw = smem_raw + w * SPANB;
    unsigned sb;
    asm("{ .reg .u64 t; cvta.to.shared.u64 t, %1; cvt.u32.u64 %0, t; }" : "=r"(sb) : "l"(sw));

    if (warpid == 0 && lane == 0) g_fail2 = 0;

    LOADW

    for (int it = 0; it < SPW; ++it) {
        const long wc0 = (warpid * SPW + it) * CHW;   // first chunk of this span
        const char* gbase = (const char*)x + (wc0 - 1) * 768L;
        const bool e0 = (wc0 == 0);

        // ---- stage 33 rows x 768B in 4 groups: pieces {2,3},{4,5},{6,7},{0,1} ----
        auto stage_pair = [&](int p0){
            #pragma unroll
            for (int k = 0; k < 13; ++k) {
                int idx = k * 32 + lane;              // 0..395 (33 rows x 12 float4)
                if (idx < 396) {
                    int r = idx / 12;
                    int o = idx - r * 12;
                    int pp = (o >= 6) ? p0 + 1 : p0;
                    int f4 = (o >= 6) ? o - 6 : o;
                    unsigned dst = sb + r * ROWB + pp * 96 + f4 * 16;
                    const char* src = gbase + (long)r * 768 + pp * 96 + f4 * 16;
                    int sz = 16;
                    if (e0 && r == 0) { src = (const char*)x; sz = 0; }  // zero row 0
                    asm volatile("cp.async.cg.shared.global [%0], [%1], 16, %2;"
                                 :: "r"(dst), "l"(src), "r"(sz));
                }
            }
            asm volatile("cp.async.commit_group;" ::: "memory");
        };
        stage_pair(2); stage_pair(4); stage_pair(6); stage_pair(0);

        // ---- warmup (prev-chunk pieces 2..7) interleaved with staging waits ----
        float lo0=0.f, lo1=0.f, lo2=0.f, hi0=1.f, hi1=1.f, hi2=1.f;
        const char* wrow = sw + lane * ROWB;
        bool col = false, ucol = false;
        WAITG(3); WARMP(2); WARMP(3);
        WAITG(2); WARMP(4); WARMP(5);
        WAITG(1); WARMP(6); WARMP(7);
        WAITG(0);

        float n0 = lo0, n1 = lo1, n2 = lo2;
        unsigned char fail = col ? 0 : 1;
        const long c = wc0 + lane;
        if (c == 0) { n0=__ldg(net0+0); n1=__ldg(net0+1); n2=__ldg(net0+2); fail = 0; }
        g_chunk_fail[c] = fail;
        __syncwarp();   // warmup reads of all rows done before preds overwrite

        // ---- main: lane t = chunk c reads row t+1; preds overwrite in place ----
        char* mrow = sw + (lane + 1) * ROWB;
        auto main_piece = [&](int j){
            const float4* pc = (const float4*)(mrow + j * 96);
            float4 c0=pc[0],c1=pc[1],c2=pc[2],c3=pc[3],c4=pc[4],c5=pc[5];
            float p0,p1,p2,p3,p4,p5,p6,p7;
            BLOCK8(OP_MAIN);
            float4* pw = (float4*)(mrow + j * 96);
            pw[0] = make_float4(p0,p1,p2,p3);
            pw[1] = make_float4(p4,p5,p6,p7);
        };
        float4* o4 = (float4*)out + wc0 * 16;
        auto gather_half = [&](int h){    // h=0: steps 0..31, h=1: steps 32..63
            #pragma unroll
            for (int k = 0; k < 8; ++k) {
                int t = k * 32 + lane;            // 0..255
                int cl  = t >> 3;                 // local chunk 0..31
                int rem = (t & 7) + h * 8;        // float4 index within chunk
                const float4* srcv = (const float4*)(sw + (cl + 1) * ROWB
                                     + (rem >> 1) * 96 + (rem & 1) * 16);
                o4[(long)cl * 16 + rem] = *srcv;
            }
        };

        main_piece(0); main_piece(1); main_piece(2); main_piece(3);
        __syncwarp();
        gather_half(0);                       // store first half while 4..7 compute
        main_piece(4); main_piece(5); main_piece(6); main_piece(7);
        __syncwarp();
        gather_half(1);
        __syncwarp();                         // buffer free before next span stages
    }
}

// Rare path: chunks whose bounds failed to collapse redo with HW2 warmup.
__global__ void fixup_kernel(const float* __restrict__ x, const float* __restrict__ W,
                             const float* __restrict__ b, const float* __restrict__ net0,
                             float* __restrict__ out, int nchunk, int nB)
{
    int c = blockIdx.x * blockDim.x + threadIdx.x;
    if (c >= nchunk) return;
    if (!g_chunk_fail[c]) return;
    long start = (long)c * LCH;

    LOADW
    long hw = start < HW2 ? start : HW2;
    const float* xp = x + 3*(start - hw);
    float lo0=0.f,lo1=0.f,lo2=0.f,hi0=1.f,hi1=1.f,hi2=1.f;
    bool col = false;
    for (long s = 0; s < hw; ++s) {
        float x0=xp[0], x1=xp[1], x2=xp[2]; xp += 3;
        MAKEV(x0,x1,x2)
        lo0=sg(lo0,v0); lo1=sg(lo1,v1); lo2=sg(lo2,v2);
        if (!col) {
            hi0=sg(hi0,v0); hi1=sg(hi1,v1); hi2=sg(hi2,v2);
            col = (lo0==hi0)&&(lo1==hi1)&&(lo2==hi2);
        }
    }
    if (!col && start > 0) atomicOr(&g_fail2, 1);
    float n0=lo0, n1=lo1, n2=lo2;
    if (start == 0) { n0=__ldg(net0+0); n1=__ldg(net0+1); n2=__ldg(net0+2); }
    long L = (start + LCH <= nB) ? LCH : (nB - start);
    for (long j = 0; j < L; ++j) {
        float x0=xp[0], x1=xp[1], x2=xp[2]; xp += 3;
        float pd; MAINSTEP(x0,x1,x2,pd);
        out[start + j] = pd;
    }
}

// Generic tail for shapes not covered by full warps (not hit for B=4M).
__global__ void edge_kernel(const float* __restrict__ x, const float* __restrict__ W,
                            const float* __restrict__ b, const float* __restrict__ net0,
                            float* __restrict__ out, long firstStep, int nB)
{
    long idx = blockIdx.x * blockDim.x + threadIdx.x;
    long start = firstStep + idx * LCH;
    if (start >= nB) return;
    LOADW
    long hw = start < HW2 ? start : HW2;
    const float* xp = x + 3*(start - hw);
    float lo0=0.f,lo1=0.f,lo2=0.f,hi0=1.f,hi1=1.f,hi2=1.f;
    bool col = false;
    for (long s = 0; s < hw; ++s) {
        float x0=xp[0], x1=xp[1], x2=xp[2]; xp += 3;
        MAKEV(x0,x1,x2)
        lo0=sg(lo0,v0); lo1=sg(lo1,v1); lo2=sg(lo2,v2);
        if (!col) {
            hi0=sg(hi0,v0); hi1=sg(hi1,v1); hi2=sg(hi2,v2);
            col = (lo0==hi0)&&(lo1==hi1)&&(lo2==hi2);
        }
    }
    if (!col && start > 0) atomicOr(&g_fail2, 1);
    float n0=lo0, n1=lo1, n2=lo2;
    if (start == 0) { n0=__ldg(net0+0); n1=__ldg(net0+1); n2=__ldg(net0+2); }
    long L = (start + LCH <= nB) ? LCH : (nB - start);
    for (long j = 0; j < L; ++j) {
        float x0=xp[0], x1=xp[1], x2=xp[2]; xp += 3;
        float pd; MAINSTEP(x0,x1,x2,pd);
        out[start + j] = pd;
    }
}

// Ultimate fallback: full serial scan (only if fixup/edge failed to collapse).
__global__ void fallback_kernel(const float* __restrict__ x, const float* __restrict__ W,
                                const float* __restrict__ b, const float* __restrict__ net0,
                                float* __restrict__ out, int nB)
{
    if (g_fail2 == 0) return;
    if (threadIdx.x != 0 || blockIdx.x != 0) return;
    LOADW
    float n0=__ldg(net0+0), n1=__ldg(net0+1), n2=__ldg(net0+2);
    const float* xp = x;
    for (int i = 0; i < nB; ++i) {
        float x0=xp[0], x1=xp[1], x2=xp[2]; xp += 3;
        float pd; MAINSTEP(x0,x1,x2,pd);
        out[i] = pd;
    }
}

extern "C" void kernel_launch(void* const* d_in, const int* in_sizes, int n_in,
                              void* d_out, int out_size)
{
    const float *x = 0, *W = 0, *b = 0, *n0p = 0;
    long nB = out_size;
    for (int i = 0; i < n_in; ++i) {
        long sz = in_sizes[i];
        if (sz == 3 * nB)      x = (const float*)d_in[i];
        else if (sz == 9)      W = (const float*)d_in[i];
        else if (sz == 3) {
            if (!b) b = (const float*)d_in[i];
            else    n0p = (const float*)d_in[i];
        }
    }
    float* out = (float*)d_out;

    long nch   = nB / LCH;                   // full chunks
    long nspan = nch / CHW;                  // full spans of 32 chunks
    long nwarp = nspan / SPW;                // warps (2 spans each)
    long nblk  = nwarp / WPB;                // blocks
    long ncov  = nblk * WPB * SPW * CHW;     // chunks covered by scan_warp
    if (ncov > 65536) { nblk = 65536 / (WPB*SPW*CHW); ncov = nblk*WPB*SPW*CHW; }
    long firstEdge = ncov * LCH;

    size_t smem = (size_t)WPB * SPANB;       // 51744 B
    cudaFuncSetAttribute(scan_warp, cudaFuncAttributeMaxDynamicSharedMemorySize, (int)smem);

    if (nblk > 0)
        scan_warp<<<(int)nblk, TPB, smem>>>(x, W, b, n0p, out);
    if (ncov > 0)
        fixup_kernel<<<(int)((ncov + 255)/256), 256>>>(x, W, b, n0p, out, (int)ncov, (int)nB);
    if (firstEdge < nB) {
        long nEdge = (nB - firstEdge + LCH - 1) / LCH;
        edge_kernel<<<(int)((nEdge + 127)/128), 128>>>(x, W, b, n0p, out, firstEdge, (int)nB);
    }
    fallback_kernel<<<1, 1>>>(x, W, b, n0p, out, (int)nB);
}

// round 11
// speedup vs baseline: 1.0097x; 1.0097x over previous
#include <cuda_runtime.h>

// 4M-step sequential sigmoid recurrence via saturation-collapse chunking.
// Warp-autonomous, halved smem footprint (13.2 KB/warp -> 16 warps/SM):
// each warp's span of 32 chunks is processed with a 4-slot (2-pair) rolling
// smem buffer; cp.async pairs stream pieces while previous pieces compute.
// Sigmoid via single-MUFU tanh.approx: sig(10t) = 0.5*tanh(5t)+0.5.
// Ladder: per-chunk fail flag -> fixup (HW2 warmup) -> serial fallback.

#define LCH   64                 // steps per chunk
#define HW2   512                // fixup warmup
#define CHW   32                 // chunks per warp-span (one per lane)
#define SPW   2                  // spans per warp (persistent)
#define WPB   2                  // warps per block
#define TPB   (WPB*32)
#define HROWB 400                // 4 slots x 96B + 16 pad (stride/16 = 25, odd)
#define NROW  (CHW+1)            // 33 rows
#define SPANB (NROW*HROWB)       // 13200 B per warp
#define C5    (5.0f)

__device__ unsigned char g_chunk_fail[65536];
__device__ int g_fail2;

__device__ __forceinline__ float tanha(float t){ float r; asm("tanh.approx.f32 %0, %1;" : "=f"(r) : "f"(t)); return r; }
__device__ __forceinline__ float sg(float n, float v){
    return fmaf(0.5f, tanha(fmaf(C5, n, v)), 0.5f);
}

#define MAKEV(x0,x1,x2) \
    float v0 = fmaf(cw00,(x0), fmaf(cw01,(x1), fmaf(cw02,(x2), cb0))); \
    float v1 = fmaf(cw10,(x0), fmaf(cw11,(x1), fmaf(cw12,(x2), cb1))); \
    float v2 = fmaf(cw20,(x0), fmaf(cw21,(x1), fmaf(cw22,(x2), cb2)));

#define LOADW \
    const float cb0 = C5*(__ldg(b+0)-0.5f), cb1 = C5*(__ldg(b+1)-0.5f), cb2 = C5*(__ldg(b+2)-0.5f); \
    const float cw00=C5*__ldg(W+0), cw01=C5*__ldg(W+1), cw02=C5*__ldg(W+2); \
    const float cw10=C5*__ldg(W+3), cw11=C5*__ldg(W+4), cw12=C5*__ldg(W+5); \
    const float cw20=C5*__ldg(W+6), cw21=C5*__ldg(W+7), cw22=C5*__ldg(W+8);

#define TWOSTEP(x0,x1,x2) do { \
    MAKEV(x0,x1,x2) \
    lo0=sg(lo0,v0); lo1=sg(lo1,v1); lo2=sg(lo2,v2); \
    hi0=sg(hi0,v0); hi1=sg(hi1,v1); hi2=sg(hi2,v2); } while(0)

#define ONESTEPW(x0,x1,x2) do { \
    MAKEV(x0,x1,x2) \
    lo0=sg(lo0,v0); lo1=sg(lo1,v1); lo2=sg(lo2,v2); } while(0)

#define MAINSTEP(x0,x1,x2,pd) do { \
    MAKEV(x0,x1,x2) \
    n0=sg(n0,v0); n1=sg(n1,v1); n2=sg(n2,v2); \
    pd = fmaf((x0),n0, fmaf((x1),n1, (x2)*n2)); } while(0)

#define BLOCK8(OP) do { \
    OP(c0.x,c0.y,c0.z,0); OP(c0.w,c1.x,c1.y,1); \
    OP(c1.z,c1.w,c2.x,2); OP(c2.y,c2.z,c2.w,3); \
    OP(c3.x,c3.y,c3.z,4); OP(c3.w,c4.x,c4.y,5); \
    OP(c4.z,c4.w,c5.x,6); OP(c5.y,c5.z,c5.w,7); } while(0)

#define OP_TWO(x0,x1,x2,j)  TWOSTEP(x0,x1,x2)
#define OP_ONE(x0,x1,x2,j)  ONESTEPW(x0,x1,x2)
#define OP_MAIN(x0,x1,x2,j) MAINSTEP(x0,x1,x2,p##j)

#define WAITG(n) asm volatile("cp.async.wait_group %0;" :: "n"(n) : "memory")
#define COMMIT   asm volatile("cp.async.commit_group;" ::: "memory")

// Warmup 2 pieces from slots sl,sl+1 of row `lane`.
#define WARM2(sl) do { \
    _Pragma("unroll") \
    for (int q = 0; q < 2; ++q) { \
        const float4* pc = (const float4*)(wrow + ((sl)+q)*96); \
        float4 c0=pc[0],c1=pc[1],c2=pc[2],c3=pc[3],c4=pc[4],c5=pc[5]; \
        if (!ucol) { BLOCK8(OP_TWO); \
            col = (lo0==hi0)&&(lo1==hi1)&&(lo2==hi2); \
            ucol = __all_sync(0xffffffffu, col); \
        } else { BLOCK8(OP_ONE); } \
    } } while(0)

// Main-compute 2 pieces from slots sl,sl+1 of row lane+1 into pr[16].
#define MAIN2(sl) do { \
    _Pragma("unroll") \
    for (int q = 0; q < 2; ++q) { \
        const float4* pc = (const float4*)(mrow + ((sl)+q)*96); \
        float4 c0=pc[0],c1=pc[1],c2=pc[2],c3=pc[3],c4=pc[4],c5=pc[5]; \
        float p0,p1,p2,p3,p4,p5,p6,p7; \
        BLOCK8(OP_MAIN); \
        float* pq = pr + q*8; \
        pq[0]=p0; pq[1]=p1; pq[2]=p2; pq[3]=p3; \
        pq[4]=p4; pq[5]=p5; pq[6]=p6; pq[7]=p7; \
    } } while(0)

// Flush pr[16] -> slots sl,sl+1 of own row, then coalesced gather to gmem.
// A pair = 2 pieces = 16 steps = 4 float4 per chunk; pair index `pair0`
// covers float4 indices [4*pair0, 4*pair0+4) of each chunk's 16-float4 output.
#define FLUSH2(sl, pair0) do { \
    __syncwarp(); \
    { float4* pw = (float4*)(mrow + (sl)*96); \
      pw[0] = make_float4(pr[0],pr[1],pr[2],pr[3]); \
      pw[1] = make_float4(pr[4],pr[5],pr[6],pr[7]); \
      float4* pw2 = (float4*)(mrow + ((sl)+1)*96); \
      pw2[0] = make_float4(pr[8],pr[9],pr[10],pr[11]); \
      pw2[1] = make_float4(pr[12],pr[13],pr[14],pr[15]); } \
    __syncwarp(); \
    _Pragma("unroll") \
    for (int k = 0; k < 4; ++k) { \
        int f = k * 32 + lane; \
        int cl  = f >> 2; \
        int rem = f & 3; \
        const float4* srcv = (const float4*)(sw + (cl + 1) * HROWB \
                             + ((sl) + (rem >> 1)) * 96 + (rem & 1) * 16); \
        o4[(long)cl * 16 + (pair0) * 4 + rem] = *srcv; \
    } \
    __syncwarp(); } while(0)

__global__ void __launch_bounds__(TPB)
scan_warp(const float* __restrict__ x, const float* __restrict__ W,
          const float* __restrict__ b, const float* __restrict__ net0,
          float* __restrict__ out)
{
    extern __shared__ char smem_raw[];
    const int w    = threadIdx.x >> 5;
    const int lane = threadIdx.x & 31;
    const long warpid = (long)blockIdx.x * WPB + w;
    char* sw = smem_raw + w * SPANB;
    unsigned sb;
    asm("{ .reg .u64 t; cvta.to.shared.u64 t, %1; cvt.u32.u64 %0, t; }" : "=r"(sb) : "l"(sw));

    if (warpid == 0 && lane == 0) g_fail2 = 0;

    LOADW

    for (int it = 0; it < SPW; ++it) {
        const long wc0 = (warpid * SPW + it) * CHW;
        const char* gbase = (const char*)x + (wc0 - 1) * 768L;
        const bool e0 = (wc0 == 0);

        // Stage pieces {p0,p0+1} of all 33 rows into slots {sl0,sl0+1}.
        auto stage_pair = [&](int p0, int sl0){
            #pragma unroll
            for (int k = 0; k < 13; ++k) {
                int idx = k * 32 + lane;              // 0..395 = 33 rows x 12 f4
                if (idx < 396) {
                    int r = idx / 12;
                    int o = idx - r * 12;
                    int half = (o >= 6);
                    int f4 = o - half * 6;
                    unsigned dst = sb + r * HROWB + (sl0 + half) * 96 + f4 * 16;
                    const char* src = gbase + (long)r * 768 + (p0 + half) * 96 + f4 * 16;
                    int sz = 16;
                    if (e0 && r == 0) { src = (const char*)x; sz = 0; }
                    asm volatile("cp.async.cg.shared.global [%0], [%1], 16, %2;"
                                 :: "r"(dst), "l"(src), "r"(sz));
                }
            }
            COMMIT;
        };

        float lo0=0.f, lo1=0.f, lo2=0.f, hi0=1.f, hi1=1.f, hi2=1.f;
        const char* wrow = sw + lane * HROWB;
        char* mrow = sw + (lane + 1) * HROWB;
        float4* o4 = (float4*)out + wc0 * 16;
        bool col = false, ucol = false;
        float pr[16];

        // ---- warmup pieces 2..7 with rolling slots ----
        stage_pair(2, 0);              // pieces 2,3 -> slots 0,1
        stage_pair(4, 2);              // pieces 4,5 -> slots 2,3
        WAITG(1);  WARM2(0);           // warm 2,3   (4,5 in flight)
        __syncwarp();
        stage_pair(6, 0);              // pieces 6,7 -> slots 0,1
        WAITG(1);  WARM2(2);           // warm 4,5   (6,7 in flight)
        __syncwarp();
        stage_pair(0, 2);              // pieces 0,1 -> slots 2,3
        WAITG(1);  WARM2(0);           // warm 6,7   (0,1 in flight)

        float n0 = lo0, n1 = lo1, n2 = lo2;
        unsigned char fail = col ? 0 : 1;
        const long c = wc0 + lane;
        if (c == 0) { n0=__ldg(net0+0); n1=__ldg(net0+1); n2=__ldg(net0+2); fail = 0; }
        g_chunk_fail[c] = fail;
        WAITG(0);
        __syncwarp();                  // all warmup reads done; slots = [6,7,0,1]

        // ---- main pieces 0..7 (pairs 0..3), rolling re-stage via slots 2,3 ----
        MAIN2(2); FLUSH2(2, 0);        // pair 0 = pieces 0,1
        stage_pair(2, 2);              // pieces 2,3 -> slots 2,3
        WAITG(0); __syncwarp();
        MAIN2(2); FLUSH2(2, 1);        // pair 1 = pieces 2,3
        stage_pair(4, 2);              // pieces 4,5 -> slots 2,3
        WAITG(0); __syncwarp();
        MAIN2(2); FLUSH2(2, 2);        // pair 2 = pieces 4,5
        MAIN2(0); FLUSH2(0, 3);        // pair 3 = pieces 6,7 (resident since warmup)
    }
}

// Rare path: chunks whose bounds failed to collapse redo with HW2 warmup.
__global__ void fixup_kernel(const float* __restrict__ x, const float* __restrict__ W,
                             const float* __restrict__ b, const float* __restrict__ net0,
                             float* __restrict__ out, int nchunk, int nB)
{
    int c = blockIdx.x * blockDim.x + threadIdx.x;
    if (c >= nchunk) return;
    if (!g_chunk_fail[c]) return;
    long start = (long)c * LCH;

    LOADW
    long hw = start < HW2 ? start : HW2;
    const float* xp = x + 3*(start - hw);
    float lo0=0.f,lo1=0.f,lo2=0.f,hi0=1.f,hi1=1.f,hi2=1.f;
    bool col = false;
    for (long s = 0; s < hw; ++s) {
        float x0=xp[0], x1=xp[1], x2=xp[2]; xp += 3;
        MAKEV(x0,x1,x2)
        lo0=sg(lo0,v0); lo1=sg(lo1,v1); lo2=sg(lo2,v2);
        if (!col) {
            hi0=sg(hi0,v0); hi1=sg(hi1,v1); hi2=sg(hi2,v2);
            col = (lo0==hi0)&&(lo1==hi1)&&(lo2==hi2);
        }
    }
    if (!col && start > 0) atomicOr(&g_fail2, 1);
    float n0=lo0, n1=lo1, n2=lo2;
    if (start == 0) { n0=__ldg(net0+0); n1=__ldg(net0+1); n2=__ldg(net0+2); }
    long L = (start + LCH <= nB) ? LCH : (nB - start);
    for (long j = 0; j < L; ++j) {
        float x0=xp[0], x1=xp[1], x2=xp[2]; xp += 3;
        float pd; MAINSTEP(x0,x1,x2,pd);
        out[start + j] = pd;
    }
}

// Generic tail for uncovered chunks (not hit for B=4M).
__global__ void edge_kernel(const float* __restrict__ x, const float* __restrict__ W,
                            const float* __restrict__ b, const float* __restrict__ net0,
                            float* __restrict__ out, long firstStep, int nB)
{
    long idx = blockIdx.x * blockDim.x + threadIdx.x;
    long start = firstStep + idx * LCH;
    if (start >= nB) return;
    LOADW
    long hw = start < HW2 ? start : HW2;
    const float* xp = x + 3*(start - hw);
    float lo0=0.f,lo1=0.f,lo2=0.f,hi0=1.f,hi1=1.f,hi2=1.f;
    bool col = false;
    for (long s = 0; s < hw; ++s) {
        float x0=xp[0], x1=xp[1], x2=xp[2]; xp += 3;
        MAKEV(x0,x1,x2)
        lo0=sg(lo0,v0); lo1=sg(lo1,v1); lo2=sg(lo2,v2);
        if (!col) {
            hi0=sg(hi0,v0); hi1=sg(hi1,v1); hi2=sg(hi2,v2);
            col = (lo0==hi0)&&(lo1==hi1)&&(lo2==hi2);
        }
    }
    if (!col && start > 0) atomicOr(&g_fail2, 1);
    float n0=lo0, n1=lo1, n2=lo2;
    if (start == 0) { n0=__ldg(net0+0); n1=__ldg(net0+1); n2=__ldg(net0+2); }
    long L = (start + LCH <= nB) ? LCH : (nB - start);
    for (long j = 0; j < L; ++j) {
        float x0=xp[0], x1=xp[1], x2=xp[2]; xp += 3;
        float pd; MAINSTEP(x0,x1,x2,pd);
        out[start + j] = pd;
    }
}

// Ultimate fallback: full serial scan.
__global__ void fallback_kernel(const float* __restrict__ x, const float* __restrict__ W,
                                const float* __restrict__ b, const float* __restrict__ net0,
                                float* __restrict__ out, int nB)
{
    if (g_fail2 == 0) return;
    if (threadIdx.x != 0 || blockIdx.x != 0) return;
    LOADW
    float n0=__ldg(net0+0), n1=__ldg(net0+1), n2=__ldg(net0+2);
    const float* xp = x;
    for (int i = 0; i < nB; ++i) {
        float x0=xp[0], x1=xp[1], x2=xp[2]; xp += 3;
        float pd; MAINSTEP(x0,x1,x2,pd);
        out[i] = pd;
    }
}

extern "C" void kernel_launch(void* const* d_in, const int* in_sizes, int n_in,
                              void* d_out, int out_size)
{
    const float *x = 0, *W = 0, *b = 0, *n0p = 0;
    long nB = out_size;
    for (int i = 0; i < n_in; ++i) {
        long sz = in_sizes[i];
        if (sz == 3 * nB)      x = (const float*)d_in[i];
        else if (sz == 9)      W = (const float*)d_in[i];
        else if (sz == 3) {
            if (!b) b = (const float*)d_in[i];
            else    n0p = (const float*)d_in[i];
        }
    }
    float* out = (float*)d_out;

    long nch   = nB / LCH;
    long nspan = nch / CHW;
    long nwarp = nspan / SPW;
    long nblk  = nwarp / WPB;
    long ncov  = nblk * WPB * SPW * CHW;
    if (ncov > 65536) { nblk = 65536 / (WPB*SPW*CHW); ncov = nblk*WPB*SPW*CHW; }
    long firstEdge = ncov * LCH;

    size_t smem = (size_t)WPB * SPANB;      // 26400 B -> 8 blocks/SM, 16 warps/SM
    cudaFuncSetAttribute(scan_warp, cudaFuncAttributeMaxDynamicSharedMemorySize, (int)smem);

    if (nblk > 0)
        scan_warp<<<(int)nblk, TPB, smem>>>(x, W, b, n0p, out);
    if (ncov > 0)
        fixup_kernel<<<(int)((ncov + 255)/256), 256>>>(x, W, b, n0p, out, (int)ncov, (int)nB);
    if (firstEdge < nB) {
        long nEdge = (nB - firstEdge + LCH - 1) / LCH;
        edge_kernel<<<(int)((nEdge + 127)/128), 128>>>(x, W, b, n0p, out, firstEdge, (int)nB);
    }
    fallback_kernel<<<1, 1>>>(x, W, b, n0p, out, (int)nB);
}

// round 12
// speedup vs baseline: 1.2284x; 1.2166x over previous
#include <cuda_runtime.h>

// 4M-step sequential sigmoid recurrence via saturation-collapse chunking.
// Simple warp-autonomous shape (low regs) + halved chunk length for occupancy:
// LCH=32, warmup = full previous chunk (already staged; zero extra DRAM).
// Each warp: stage 33 contiguous rows (400B padded) via one cp.async batch,
// warmup from row `lane`, main over row `lane+1` with in-place pred overwrite,
// coalesced gather stores. 13.2 KB/warp -> 16 warps/SM.
// Ladder: per-chunk fail flag -> fixup (HW2 warmup) -> serial fallback.

#define LCH   32                 // steps per chunk (4 pieces of 8)
#define HW2   512                // fixup warmup
#define CHW   32                 // chunks per warp (one per lane)
#define WPB   2                  // warps per block
#define TPB   (WPB*32)
#define ROWB  400                // 384 data + 16 pad (stride/16 = 25, odd)
#define NROW  (CHW+1)            // 33 rows (row 0 = previous chunk)
#define SPANB (NROW*ROWB)        // 13200 B per warp
#define NF4   (NROW*24)          // 792 float4 per span (gmem-contiguous)
#define NCHMAX 131072
#define C5    (5.0f)

__device__ unsigned char g_chunk_fail[NCHMAX];
__device__ int g_fail2;

__device__ __forceinline__ float tanha(float t){ float r; asm("tanh.approx.f32 %0, %1;" : "=f"(r) : "f"(t)); return r; }
// sigmoid(10*(n+u-0.5)) = 0.5*tanh(5n + v) + 0.5,  v = 5*(u-0.5)
__device__ __forceinline__ float sg(float n, float v){
    return fmaf(0.5f, tanha(fmaf(C5, n, v)), 0.5f);
}

#define MAKEV(x0,x1,x2) \
    float v0 = fmaf(cw00,(x0), fmaf(cw01,(x1), fmaf(cw02,(x2), cb0))); \
    float v1 = fmaf(cw10,(x0), fmaf(cw11,(x1), fmaf(cw12,(x2), cb1))); \
    float v2 = fmaf(cw20,(x0), fmaf(cw21,(x1), fmaf(cw22,(x2), cb2)));

#define LOADW \
    const float cb0 = C5*(__ldg(b+0)-0.5f), cb1 = C5*(__ldg(b+1)-0.5f), cb2 = C5*(__ldg(b+2)-0.5f); \
    const float cw00=C5*__ldg(W+0), cw01=C5*__ldg(W+1), cw02=C5*__ldg(W+2); \
    const float cw10=C5*__ldg(W+3), cw11=C5*__ldg(W+4), cw12=C5*__ldg(W+5); \
    const float cw20=C5*__ldg(W+6), cw21=C5*__ldg(W+7), cw22=C5*__ldg(W+8);

#define TWOSTEP(x0,x1,x2) do { \
    MAKEV(x0,x1,x2) \
    lo0=sg(lo0,v0); lo1=sg(lo1,v1); lo2=sg(lo2,v2); \
    hi0=sg(hi0,v0); hi1=sg(hi1,v1); hi2=sg(hi2,v2); } while(0)

#define ONESTEPW(x0,x1,x2) do { \
    MAKEV(x0,x1,x2) \
    lo0=sg(lo0,v0); lo1=sg(lo1,v1); lo2=sg(lo2,v2); } while(0)

#define MAINSTEP(x0,x1,x2,pd) do { \
    MAKEV(x0,x1,x2) \
    n0=sg(n0,v0); n1=sg(n1,v1); n2=sg(n2,v2); \
    pd = fmaf((x0),n0, fmaf((x1),n1, (x2)*n2)); } while(0)

#define BLOCK8(OP) do { \
    OP(c0.x,c0.y,c0.z,0); OP(c0.w,c1.x,c1.y,1); \
    OP(c1.z,c1.w,c2.x,2); OP(c2.y,c2.z,c2.w,3); \
    OP(c3.x,c3.y,c3.z,4); OP(c3.w,c4.x,c4.y,5); \
    OP(c4.z,c4.w,c5.x,6); OP(c5.y,c5.z,c5.w,7); } while(0)

#define OP_TWO(x0,x1,x2,j)  TWOSTEP(x0,x1,x2)
#define OP_ONE(x0,x1,x2,j)  ONESTEPW(x0,x1,x2)
#define OP_MAIN(x0,x1,x2,j) MAINSTEP(x0,x1,x2,p##j)

__global__ void __launch_bounds__(TPB)
scan_warp(const float* __restrict__ x, const float* __restrict__ W,
          const float* __restrict__ b, const float* __restrict__ net0,
          float* __restrict__ out)
{
    extern __shared__ char smem_raw[];
    const int w    = threadIdx.x >> 5;
    const int lane = threadIdx.x & 31;
    const long warpid = (long)blockIdx.x * WPB + w;
    const long wc0 = warpid * CHW;            // first chunk owned by this warp
    char* sw = smem_raw + w * SPANB;
    unsigned sb;
    asm("{ .reg .u64 t; cvta.to.shared.u64 t, %1; cvt.u32.u64 %0, t; }" : "=r"(sb) : "l"(sw));

    if (warpid == 0 && lane == 0) g_fail2 = 0;

    // ---- stage span: chunks [wc0-1, wc0+32), 33 rows x 384B (contiguous gmem) ----
    const char* gbase = (const char*)x + (wc0 - 1) * 384L;
    const bool e0 = (wc0 == 0);
    #pragma unroll
    for (int k = 0; k < (NF4 + 31) / 32; ++k) {
        int idx = k * 32 + lane;
        if (idx < NF4) {
            int r = idx / 24, o = idx - r * 24;
            unsigned dst = sb + r * ROWB + o * 16;
            const char* src = gbase + (long)idx * 16;
            int sz = 16;
            if (e0 && idx < 24) { src = (const char*)x; sz = 0; }   // zero row 0
            asm volatile("cp.async.cg.shared.global [%0], [%1], 16, %2;"
                         :: "r"(dst), "l"(src), "r"(sz));
        }
    }
    asm volatile("cp.async.commit_group;" ::: "memory");

    LOADW   // overlap weight loads with the copy

    asm volatile("cp.async.wait_group 0;" ::: "memory");
    __syncwarp();

    // ---- warmup: lane t reads row t (= chunk c-1), pieces 0..3 (32 steps) ----
    float lo0=0.f, lo1=0.f, lo2=0.f, hi0=1.f, hi1=1.f, hi2=1.f;
    const char* wrow = sw + lane * ROWB;
    bool col = false, ucol = false;
    #pragma unroll
    for (int p = 0; p < 4; ++p) {
        const float4* pc = (const float4*)(wrow + p * 96);
        float4 c0=pc[0], c1=pc[1], c2=pc[2], c3=pc[3], c4=pc[4], c5=pc[5];
        if (!ucol) {
            BLOCK8(OP_TWO);
            col  = (lo0==hi0) && (lo1==hi1) && (lo2==hi2);
            ucol = __all_sync(0xffffffffu, col);
        } else {
            BLOCK8(OP_ONE);
        }
    }
    float n0 = lo0, n1 = lo1, n2 = lo2;
    unsigned char fail = col ? 0 : 1;
    const long c = wc0 + lane;
    if (c == 0) { n0=__ldg(net0+0); n1=__ldg(net0+1); n2=__ldg(net0+2); fail = 0; }
    g_chunk_fail[c] = fail;
    __syncwarp();   // all warmup reads done before preds overwrite rows

    // ---- main: lane t reads row t+1 (= chunk c); preds overwrite in place ----
    // Piece j consumes 96B (24 floats); its 8 preds (2 f4) overwrite bytes [0,32).
    char* mrow = sw + (lane + 1) * ROWB;
    #pragma unroll
    for (int j = 0; j < 4; ++j) {
        const float4* pc = (const float4*)(mrow + j * 96);
        float4 c0=pc[0], c1=pc[1], c2=pc[2], c3=pc[3], c4=pc[4], c5=pc[5];
        float p0,p1,p2,p3,p4,p5,p6,p7;
        BLOCK8(OP_MAIN);
        float4* pw = (float4*)(mrow + j * 96);
        pw[0] = make_float4(p0,p1,p2,p3);
        pw[1] = make_float4(p4,p5,p6,p7);
    }
    __syncwarp();   // preds visible warp-wide before cross-lane gather

    // ---- coalesced output: 256 float4 = 32 chunks x 8 float4 ----
    float4* o4 = (float4*)out + wc0 * 8;
    #pragma unroll
    for (int k = 0; k < 8; ++k) {
        int f = k * 32 + lane;            // 0..255
        int cl  = f >> 3;                 // local chunk
        int rem = f & 7;                  // pred f4 within chunk
        const float4* srcv = (const float4*)(sw + (cl + 1) * ROWB
                             + (rem >> 1) * 96 + (rem & 1) * 16);
        o4[f] = *srcv;
    }
}

// Rare path: chunks whose bounds failed to collapse redo with HW2 warmup.
__global__ void fixup_kernel(const float* __restrict__ x, const float* __restrict__ W,
                             const float* __restrict__ b, const float* __restrict__ net0,
                             float* __restrict__ out, int nchunk, int nB)
{
    int c = blockIdx.x * blockDim.x + threadIdx.x;
    if (c >= nchunk) return;
    if (!g_chunk_fail[c]) return;
    long start = (long)c * LCH;

    LOADW
    long hw = start < HW2 ? start : HW2;
    const float* xp = x + 3*(start - hw);
    float lo0=0.f,lo1=0.f,lo2=0.f,hi0=1.f,hi1=1.f,hi2=1.f;
    bool col = false;
    for (long s = 0; s < hw; ++s) {
        float x0=xp[0], x1=xp[1], x2=xp[2]; xp += 3;
        MAKEV(x0,x1,x2)
        lo0=sg(lo0,v0); lo1=sg(lo1,v1); lo2=sg(lo2,v2);
        if (!col) {
            hi0=sg(hi0,v0); hi1=sg(hi1,v1); hi2=sg(hi2,v2);
            col = (lo0==hi0)&&(lo1==hi1)&&(lo2==hi2);
        }
    }
    if (!col && start > 0) atomicOr(&g_fail2, 1);
    float n0=lo0, n1=lo1, n2=lo2;
    if (start == 0) { n0=__ldg(net0+0); n1=__ldg(net0+1); n2=__ldg(net0+2); }
    long L = (start + LCH <= nB) ? LCH : (nB - start);
    for (long j = 0; j < L; ++j) {
        float x0=xp[0], x1=xp[1], x2=xp[2]; xp += 3;
        float pd; MAINSTEP(x0,x1,x2,pd);
        out[start + j] = pd;
    }
}

// Generic tail for uncovered chunks (not hit for B=4M).
__global__ void edge_kernel(const float* __restrict__ x, const float* __restrict__ W,
                            const float* __restrict__ b, const float* __restrict__ net0,
                            float* __restrict__ out, long firstStep, int nB)
{
    long idx = blockIdx.x * blockDim.x + threadIdx.x;
    long start = firstStep + idx * LCH;
    if (start >= nB) return;
    LOADW
    long hw = start < HW2 ? start : HW2;
    const float* xp = x + 3*(start - hw);
    float lo0=0.f,lo1=0.f,lo2=0.f,hi0=1.f,hi1=1.f,hi2=1.f;
    bool col = false;
    for (long s = 0; s < hw; ++s) {
        float x0=xp[0], x1=xp[1], x2=xp[2]; xp += 3;
        MAKEV(x0,x1,x2)
        lo0=sg(lo0,v0); lo1=sg(lo1,v1); lo2=sg(lo2,v2);
        if (!col) {
            hi0=sg(hi0,v0); hi1=sg(hi1,v1); hi2=sg(hi2,v2);
            col = (lo0==hi0)&&(lo1==hi1)&&(lo2==hi2);
        }
    }
    if (!col && start > 0) atomicOr(&g_fail2, 1);
    float n0=lo0, n1=lo1, n2=lo2;
    if (start == 0) { n0=__ldg(net0+0); n1=__ldg(net0+1); n2=__ldg(net0+2); }
    long L = (start + LCH <= nB) ? LCH : (nB - start);
    for (long j = 0; j < L; ++j) {
        float x0=xp[0], x1=xp[1], x2=xp[2]; xp += 3;
        float pd; MAINSTEP(x0,x1,x2,pd);
        out[start + j] = pd;
    }
}

// Ultimate fallback: full serial scan.
__global__ void fallback_kernel(const float* __restrict__ x, const float* __restrict__ W,
                                const float* __restrict__ b, const float* __restrict__ net0,
                                float* __restrict__ out, int nB)
{
    if (g_fail2 == 0) return;
    if (threadIdx.x != 0 || blockIdx.x != 0) return;
    LOADW
    float n0=__ldg(net0+0), n1=__ldg(net0+1), n2=__ldg(net0+2);
    const float* xp = x;
    for (int i = 0; i < nB; ++i) {
        float x0=xp[0], x1=xp[1], x2=xp[2]; xp += 3;
        float pd; MAINSTEP(x0,x1,x2,pd);
        out[i] = pd;
    }
}

extern "C" void kernel_launch(void* const* d_in, const int* in_sizes, int n_in,
                              void* d_out, int out_size)
{
    const float *x = 0, *W = 0, *b = 0, *n0p = 0;
    long nB = out_size;
    for (int i = 0; i < n_in; ++i) {
        long sz = in_sizes[i];
        if (sz == 3 * nB)      x = (const float*)d_in[i];
        else if (sz == 9)      W = (const float*)d_in[i];
        else if (sz == 3) {
            if (!b) b = (const float*)d_in[i];
            else    n0p = (const float*)d_in[i];
        }
    }
    float* out = (float*)d_out;

    long nch   = nB / LCH;                 // full chunks (B=4M -> 131072)
    long nwarp = nch / CHW;                // warps of 32 chunks
    long nblk  = nwarp / WPB;              // blocks
    long ncov  = nblk * WPB * CHW;         // chunks covered by scan_warp
    if (ncov > NCHMAX) { nblk = NCHMAX / (WPB*CHW); ncov = nblk*WPB*CHW; }
    long firstEdge = ncov * LCH;

    size_t smem = (size_t)WPB * SPANB;     // 26400 B -> 8 blocks/SM, 16 warps/SM
    cudaFuncSetAttribute(scan_warp, cudaFuncAttributeMaxDynamicSharedMemorySize, (int)smem);

    if (nblk > 0)
        scan_warp<<<(int)nblk, TPB, smem>>>(x, W, b, n0p, out);
    if (ncov > 0)
        fixup_kernel<<<(int)((ncov + 255)/256), 256>>>(x, W, b, n0p, out, (int)ncov, (int)nB);
    if (firstEdge < nB) {
        long nEdge = (nB - firstEdge + LCH - 1) / LCH;
        edge_kernel<<<(int)((nEdge + 127)/128), 128>>>(x, W, b, n0p, out, firstEdge, (int)nB);
    }
    fallback_kernel<<<1, 1>>>(x, W, b, n0p, out, (int)nB);
}